// round 3
// baseline (speedup 1.0000x reference)
#include <cuda_runtime.h>
#include <cuda_fp16.h>
#include <cstdint>

// ---------------------------------------------------------------------------
// out[8192,4096] = x[8192,4096] @ dequantNF4(qweight,scales)[4096,4096] + bias
// Harness PTX target is sm_100 (no 'a' suffix) => NO tcgen05. Use classic
// mma.sync.m16n8k16 f16 tensor cores with a 4-stage cp.async pipeline.
// fp16 operands carry 10 mantissa bits (== tf32) -> rel_err ~4e-4 < 1e-3.
// ---------------------------------------------------------------------------
#define MDIM 8192
#define NDIM 4096
#define KDIM 4096
#define KWROWS (KDIM / 8)

#define BM 128
#define BN 256
#define BK 64                          // fp16 elems / K-chunk: 128-byte rows
#define STAGES 4
#define NITER (KDIM / BK)              // 64
#define A_BYTES (BM * BK * 2)          // 16384
#define B_BYTES (BN * BK * 2)          // 32768
#define STAGE_BYTES (A_BYTES + B_BYTES)            // 49152
#define SMEM_TOTAL (1024 + STAGES * STAGE_BYTES)   // 197632

// SW128 swizzle for 128-byte rows (Swizzle<3,4,3>)
#define SWZ(bo) ((bo) ^ (((bo) >> 3) & 0x70))

// ---------------------------------------------------------------------------
// Scratch
// ---------------------------------------------------------------------------
__device__ __align__(16) __half g_X[(size_t)MDIM * KDIM];   // [M,K]
__device__ __align__(16) __half g_W[(size_t)NDIM * KDIM];   // [N,K] K-major

__device__ const float NF4_TBL[16] = {
    -1.0f, -0.6961928009986877f, -0.5250730514526367f, -0.39491748809814453f,
    -0.28444138169288635f, -0.18477343022823334f, -0.09105003625154495f, 0.0f,
    0.07958029955625534f, 0.16093020141124725f, 0.24611230194568634f,
    0.33791524171829224f, 0.44070982933044434f, 0.5626170039176941f,
    0.7229568362236023f, 1.0f};

// ---------------------------------------------------------------------------
// Helpers
// ---------------------------------------------------------------------------
__device__ __forceinline__ uint32_t smem_u32(const void* p) {
    uint32_t a;
    asm("{ .reg .u64 t; cvta.to.shared.u64 t, %1; cvt.u32.u64 %0, t; }"
        : "=r"(a) : "l"(p));
    return a;
}

#define CP_ASYNC16(smem, gptr) \
    asm volatile("cp.async.cg.shared.global [%0], [%1], 16;" \
                 :: "r"(smem), "l"(gptr) : "memory")

#define LDSM4(r, addr)                                                         \
    asm volatile("ldmatrix.sync.aligned.m8n8.x4.shared.b16 {%0,%1,%2,%3}, [%4];" \
                 : "=r"((r)[0]), "=r"((r)[1]), "=r"((r)[2]), "=r"((r)[3])      \
                 : "r"(addr))

#define MMA16816(c, a, b0, b1)                                                 \
    asm volatile("mma.sync.aligned.m16n8k16.row.col.f32.f16.f16.f32 "          \
                 "{%0,%1,%2,%3}, {%4,%5,%6,%7}, {%8,%9}, {%0,%1,%2,%3};"       \
                 : "+f"((c)[0]), "+f"((c)[1]), "+f"((c)[2]), "+f"((c)[3])      \
                 : "r"((a)[0]), "r"((a)[1]), "r"((a)[2]), "r"((a)[3]),         \
                   "r"(b0), "r"(b1))

// ---------------------------------------------------------------------------
// Kernel 1: x (fp32) -> g_X (fp16), 8 elems/thread
// ---------------------------------------------------------------------------
__global__ void __launch_bounds__(256) round_x_kernel(const float4* __restrict__ x) {
    int i = blockIdx.x * 256 + threadIdx.x;
    float4 a = x[2 * i];
    float4 b = x[2 * i + 1];
    __half2 h[4];
    h[0] = __floats2half2_rn(a.x, a.y);
    h[1] = __floats2half2_rn(a.z, a.w);
    h[2] = __floats2half2_rn(b.x, b.y);
    h[3] = __floats2half2_rn(b.z, b.w);
    reinterpret_cast<float4*>(g_X)[i] = *reinterpret_cast<float4*>(h);
}

// ---------------------------------------------------------------------------
// Kernel 2: dequant NF4 -> g_W (fp16, [N,K] K-major)
// ---------------------------------------------------------------------------
__global__ void __launch_bounds__(256) dequant_kernel(const int* __restrict__ qw,
                                                      const float* __restrict__ sc) {
    int gid = blockIdx.x * 256 + threadIdx.x;
    int kw = gid >> 12;                      // NDIM = 4096
    int n  = gid & (NDIM - 1);
    uint32_t q = (uint32_t)qw[(size_t)kw * NDIM + n];
    float s = sc[(size_t)(kw >> 4) * NDIM + n];
    __half2 h[4];
#pragma unroll
    for (int j = 0; j < 4; ++j) {
        float lo = NF4_TBL[(q >> (8 * j)) & 15] * s;
        float hi = NF4_TBL[(q >> (8 * j + 4)) & 15] * s;
        h[j] = __floats2half2_rn(lo, hi);
    }
    *reinterpret_cast<float4*>(g_W + (size_t)n * KDIM + kw * 8) =
        *reinterpret_cast<float4*>(h);
}

// ---------------------------------------------------------------------------
// Kernel 3: multistage mma.sync GEMM, 128x256 CTA tile, 8 warps (2x4),
// warp tile 64x64.
// ---------------------------------------------------------------------------
__global__ void __launch_bounds__(256, 1) gemm_f16(const float* __restrict__ bias,
                                                   float* __restrict__ out) {
    extern __shared__ char smem_raw[];
    const uint32_t sb = (smem_u32(smem_raw) + 1023) & ~1023u;  // 1KB-align tiles
    const int tid  = threadIdx.x;
    const int wid  = tid >> 5;
    const int lane = tid & 31;
    const int tile_n = blockIdx.x;
    const int tile_m = blockIdx.y;
    const int wm = wid >> 2;                 // 0..1  -> m offset wm*64
    const int wn = wid & 3;                  // 0..3  -> n offset wn*64

    // ---- per-thread cp.async offsets (A: 4 chunks, B: 8 chunks of 16B) ----
    uint32_t a_sw[4], b_sw[8];
    int a_go[4], b_go[8];
#pragma unroll
    for (int j = 0; j < 4; ++j) {
        int c = tid + j * 256;               // 1024 A chunks
        int r = c >> 3, ci = c & 7;
        uint32_t bo = (uint32_t)(r * 128 + ci * 16);
        a_sw[j] = SWZ(bo);
        a_go[j] = r * KDIM + ci * 8;
    }
#pragma unroll
    for (int j = 0; j < 8; ++j) {
        int c = tid + j * 256;               // 2048 B chunks
        int r = c >> 3, ci = c & 7;
        uint32_t bo = (uint32_t)(r * 128 + ci * 16);
        b_sw[j] = (uint32_t)A_BYTES + SWZ(bo);
        b_go[j] = r * KDIM + ci * 8;
    }
    const __half* Ab = g_X + (size_t)tile_m * BM * KDIM;
    const __half* Bb = g_W + (size_t)tile_n * BN * KDIM;

    // ---- prologue: fill STAGES-1 stages ----
#pragma unroll
    for (int s = 0; s < STAGES - 1; ++s) {
        uint32_t stb = sb + s * STAGE_BYTES;
        const __half* ap = Ab + s * BK;
        const __half* bp = Bb + s * BK;
#pragma unroll
        for (int j = 0; j < 4; ++j) CP_ASYNC16(stb + a_sw[j], ap + a_go[j]);
#pragma unroll
        for (int j = 0; j < 8; ++j) CP_ASYNC16(stb + b_sw[j], bp + b_go[j]);
        asm volatile("cp.async.commit_group;" ::: "memory");
    }

    float acc[4][8][4];
#pragma unroll
    for (int i = 0; i < 4; ++i)
#pragma unroll
        for (int j = 0; j < 8; ++j)
#pragma unroll
            for (int k = 0; k < 4; ++k) acc[i][j][k] = 0.0f;

    // ldmatrix per-lane row/col components (constant across iterations)
    const int a_row_base = wm * 64 + (lane & 15);        // + mt*16
    const uint32_t a_kh  = (uint32_t)((lane >> 4) << 4); // k-half byte sel
    const int b_row_base = wn * 64 + ((lane >> 4) << 3) + (lane & 7); // + nt*16
    const uint32_t b_kh  = (uint32_t)(((lane >> 3) & 1) << 4);

#pragma unroll 1
    for (int it = 0; it < NITER; ++it) {
        asm volatile("cp.async.wait_group %0;" :: "n"(STAGES - 2) : "memory");
        __syncthreads();

        // issue loads for stage it+STAGES-1
        int nx = it + STAGES - 1;
        if (nx < NITER) {
            uint32_t stb = sb + (nx & (STAGES - 1)) * STAGE_BYTES;
            const __half* ap = Ab + nx * BK;
            const __half* bp = Bb + nx * BK;
#pragma unroll
            for (int j = 0; j < 4; ++j) CP_ASYNC16(stb + a_sw[j], ap + a_go[j]);
#pragma unroll
            for (int j = 0; j < 8; ++j) CP_ASYNC16(stb + b_sw[j], bp + b_go[j]);
        }
        asm volatile("cp.async.commit_group;" ::: "memory");

        // compute on stage it
        const uint32_t stb = sb + (it & (STAGES - 1)) * STAGE_BYTES;
#pragma unroll
        for (int ks = 0; ks < 4; ++ks) {
            uint32_t a[4][4];
#pragma unroll
            for (int mt = 0; mt < 4; ++mt) {
                uint32_t bo = (uint32_t)((a_row_base + mt * 16) * 128 + ks * 32) + a_kh;
                LDSM4(a[mt], stb + SWZ(bo));
            }
            uint32_t b[4][4];
#pragma unroll
            for (int nt = 0; nt < 4; ++nt) {
                uint32_t bo = (uint32_t)((b_row_base + nt * 16) * 128 + ks * 32) + b_kh;
                LDSM4(b[nt], stb + (uint32_t)A_BYTES + SWZ(bo));
            }
#pragma unroll
            for (int mt = 0; mt < 4; ++mt)
#pragma unroll
                for (int j = 0; j < 8; ++j)
                    MMA16816(acc[mt][j], a[mt], b[j >> 1][(j & 1) * 2],
                             b[j >> 1][(j & 1) * 2 + 1]);
        }
    }

    // ---- epilogue: bias + store (no smem needed) ----
    const int m0 = tile_m * BM + wm * 64 + (lane >> 2);
    const int n0 = tile_n * BN + wn * 64 + 2 * (lane & 3);
#pragma unroll
    for (int j = 0; j < 8; ++j) {
        const int n = n0 + j * 8;
        const float2 bv = *reinterpret_cast<const float2*>(bias + n);
#pragma unroll
        for (int mt = 0; mt < 4; ++mt) {
            const int m = m0 + mt * 16;
            float2 v0, v1;
            v0.x = acc[mt][j][0] + bv.x;
            v0.y = acc[mt][j][1] + bv.y;
            v1.x = acc[mt][j][2] + bv.x;
            v1.y = acc[mt][j][3] + bv.y;
            *reinterpret_cast<float2*>(out + (size_t)m * NDIM + n) = v0;
            *reinterpret_cast<float2*>(out + (size_t)(m + 8) * NDIM + n) = v1;
        }
    }
}

// ---------------------------------------------------------------------------
// Launch
// ---------------------------------------------------------------------------
extern "C" void kernel_launch(void* const* d_in, const int* in_sizes, int n_in,
                              void* d_out, int out_size) {
    const float* x       = (const float*)d_in[0];   // [8192, 4096]
    const float* scales  = (const float*)d_in[1];   // [32, 4096]
    const float* bias    = (const float*)d_in[2];   // [4096]
    const int*   qweight = (const int*)d_in[3];     // [512, 4096]
    float* out = (float*)d_out;

    cudaFuncSetAttribute(gemm_f16, cudaFuncAttributeMaxDynamicSharedMemorySize,
                         SMEM_TOTAL);

    round_x_kernel<<<(MDIM * KDIM / 8) / 256, 256>>>((const float4*)x);
    dequant_kernel<<<(KWROWS * NDIM) / 256, 256>>>(qweight, scales);
    gemm_f16<<<dim3(NDIM / BN, MDIM / BM), 256, SMEM_TOTAL>>>(bias, out);
}